// round 1
// baseline (speedup 1.0000x reference)
#include <cuda_runtime.h>
#include <cstdint>

#define N_NODES 100000
#define N_EDGES 1600000
#define D 128

// Scratch (device globals: runtime allocation is forbidden)
__device__ float g_neigh[(size_t)N_NODES * D];  // sum_e w_e * nfeat[src]
__device__ float g_esum [(size_t)N_NODES * D];  // sum_e efeat[e]
__device__ float g_deg  [N_NODES];              // in-degree (float)

// ---------------------------------------------------------------------------
// Vectorized fp32 reduction (no return) — sm_90+
// ---------------------------------------------------------------------------
__device__ __forceinline__ void red_add_v4(float* addr, float4 v) {
    asm volatile("red.global.add.v4.f32 [%0], {%1, %2, %3, %4};"
                 :: "l"(addr), "f"(v.x), "f"(v.y), "f"(v.z), "f"(v.w)
                 : "memory");
}

// ---------------------------------------------------------------------------
// Kernel 1: zero the accumulators
// ---------------------------------------------------------------------------
__global__ void zero_kernel() {
    const size_t total4 = (size_t)N_NODES * D / 4;  // 3.2M float4 per array
    size_t i = (size_t)blockIdx.x * blockDim.x + threadIdx.x;
    float4 z = make_float4(0.f, 0.f, 0.f, 0.f);
    if (i < total4) {
        reinterpret_cast<float4*>(g_neigh)[i] = z;
        reinterpret_cast<float4*>(g_esum)[i]  = z;
    }
    if (i < N_NODES) g_deg[i] = 0.f;
}

// ---------------------------------------------------------------------------
// Kernel 2: edge scatter. One warp per edge; lane l owns float4 chunk l.
// ---------------------------------------------------------------------------
__global__ __launch_bounds__(256) void scatter_kernel(
    const float* __restrict__ nfeat,
    const float* __restrict__ efeat,
    const float* __restrict__ ew,
    const int*   __restrict__ src,
    const int*   __restrict__ dst)
{
    const int gtid = blockIdx.x * blockDim.x + threadIdx.x;
    const int e    = gtid >> 5;
    const int lane = threadIdx.x & 31;
    if (e >= N_EDGES) return;

    const int   s = __ldg(src + e);
    const int   d = __ldg(dst + e);
    const float w = __ldg(ew  + e);

    const float4 nf = __ldg(reinterpret_cast<const float4*>(nfeat + (size_t)s * D) + lane);
    const float4 ef = __ldg(reinterpret_cast<const float4*>(efeat + (size_t)e * D) + lane);

    float4 m = make_float4(nf.x * w, nf.y * w, nf.z * w, nf.w * w);

    red_add_v4(g_neigh + (size_t)d * D + lane * 4, m);
    red_add_v4(g_esum  + (size_t)d * D + lane * 4, ef);
    if (lane == 0) atomicAdd(g_deg + d, 1.0f);
}

// ---------------------------------------------------------------------------
// Kernel 3: fused normalize + GEMM + bias.
//   x1[n] = (neigh[n] + 2*nfeat[n]) / (deg[n]+1)
//   x2[n] = esum[n] / max(deg[n],1)
//   out[n] = x1[n] @ Wn^T + x2[n] @ We^T + b_neigh + (deg[n]>0)*b_edge
// Tiled sgemm: BM=64 nodes, BN=128 (full width), BK=32, K=256 (concat).
// Thread tile 8x4, 256 threads. Within a warp, all lanes share the same
// 8 rows (As reads are pure smem broadcast) and read distinct Bs float4s
// (conflict-free).
// ---------------------------------------------------------------------------
__global__ __launch_bounds__(256) void gemm_kernel(
    const float* __restrict__ nfeat,
    const float* __restrict__ Wn,
    const float* __restrict__ bn,
    const float* __restrict__ We,
    const float* __restrict__ be,
    float*       __restrict__ out)
{
    __shared__ float As[32][64];    // x^T tile
    __shared__ float Bs[32][128];   // W^T tile
    __shared__ float s_rd1[64], s_rd2[64], s_flag[64];

    const int tid = threadIdx.x;
    const int n0  = blockIdx.x * 64;

    if (tid < 64) {
        int n = n0 + tid;
        float dg = (n < N_NODES) ? g_deg[n] : 0.f;
        s_rd1[tid]  = 1.f / (dg + 1.f);
        s_rd2[tid]  = 1.f / fmaxf(dg, 1.f);
        s_flag[tid] = (dg > 0.f) ? 1.f : 0.f;
    }
    __syncthreads();

    float acc[8][4];
#pragma unroll
    for (int i = 0; i < 8; i++)
#pragma unroll
        for (int j = 0; j < 4; j++) acc[i][j] = 0.f;

    const int tr = tid >> 5;   // warp id: rows tr*8 .. tr*8+7
    const int tc = tid & 31;   // lane: cols tc*4 .. tc*4+3

    // x-tile loader mapping: 8 floats (2 float4) per thread
    const int  lm   = tid >> 2;          // node-in-tile 0..63
    const int  lv   = tid & 3;
    const int  ln   = n0 + lm;
    const bool lval = ln < N_NODES;
    const float rd1 = s_rd1[lm];
    const float rd2 = s_rd2[lm];

    // W-tile loader mapping: 16 floats (4 float4) per thread
    const int wj = tid >> 1;             // output col 0..127
    const int wv = tid & 1;

#pragma unroll 1
    for (int k0 = 0; k0 < 256; k0 += 32) {
        const bool half1 = (k0 < 128);
        const int  kbase = half1 ? k0 : (k0 - 128);

        // ---- load x tile (transposed into As) ----
#pragma unroll
        for (int t = 0; t < 2; t++) {
            const int kk = lv * 4 + t * 16;
            float4 v = make_float4(0.f, 0.f, 0.f, 0.f);
            if (lval) {
                const size_t off = (size_t)ln * D + kbase + kk;
                if (half1) {
                    float4 a = *reinterpret_cast<const float4*>(g_neigh + off);
                    float4 b = __ldg(reinterpret_cast<const float4*>(nfeat + off));
                    v.x = (a.x + 2.f * b.x) * rd1;
                    v.y = (a.y + 2.f * b.y) * rd1;
                    v.z = (a.z + 2.f * b.z) * rd1;
                    v.w = (a.w + 2.f * b.w) * rd1;
                } else {
                    float4 a = *reinterpret_cast<const float4*>(g_esum + off);
                    v.x = a.x * rd2; v.y = a.y * rd2;
                    v.z = a.z * rd2; v.w = a.w * rd2;
                }
            }
            As[kk + 0][lm] = v.x;
            As[kk + 1][lm] = v.y;
            As[kk + 2][lm] = v.z;
            As[kk + 3][lm] = v.w;
        }

        // ---- load W tile (transposed into Bs) ----
        const float* Wp = half1 ? Wn : We;
#pragma unroll
        for (int q = 0; q < 4; q++) {
            const int kk = wv * 16 + q * 4;
            float4 v = __ldg(reinterpret_cast<const float4*>(Wp + (size_t)wj * D + kbase + kk));
            Bs[kk + 0][wj] = v.x;
            Bs[kk + 1][wj] = v.y;
            Bs[kk + 2][wj] = v.z;
            Bs[kk + 3][wj] = v.w;
        }
        __syncthreads();

        // ---- compute ----
#pragma unroll
        for (int kk = 0; kk < 32; kk++) {
            const float4 b4 = *reinterpret_cast<const float4*>(&Bs[kk][tc * 4]);
#pragma unroll
            for (int i = 0; i < 8; i++) {
                const float a = As[kk][tr * 8 + i];
                acc[i][0] += a * b4.x;
                acc[i][1] += a * b4.y;
                acc[i][2] += a * b4.z;
                acc[i][3] += a * b4.w;
            }
        }
        __syncthreads();
    }

    // ---- epilogue: biases + store ----
    const float4 bnv = __ldg(reinterpret_cast<const float4*>(bn + tc * 4));
    const float4 bev = __ldg(reinterpret_cast<const float4*>(be + tc * 4));
#pragma unroll
    for (int i = 0; i < 8; i++) {
        const int n = n0 + tr * 8 + i;
        if (n < N_NODES) {
            const float f = s_flag[tr * 8 + i];
            float4 o;
            o.x = acc[i][0] + bnv.x + f * bev.x;
            o.y = acc[i][1] + bnv.y + f * bev.y;
            o.z = acc[i][2] + bnv.z + f * bev.z;
            o.w = acc[i][3] + bnv.w + f * bev.w;
            *reinterpret_cast<float4*>(out + (size_t)n * D + tc * 4) = o;
        }
    }
}

// ---------------------------------------------------------------------------
extern "C" void kernel_launch(void* const* d_in, const int* in_sizes, int n_in,
                              void* d_out, int out_size) {
    const float* nfeat = (const float*)d_in[0];
    const float* efeat = (const float*)d_in[1];
    const float* ew    = (const float*)d_in[2];
    const float* Wn    = (const float*)d_in[3];
    const float* bn    = (const float*)d_in[4];
    const float* We    = (const float*)d_in[5];
    const float* be    = (const float*)d_in[6];
    const int*   src   = (const int*)d_in[7];
    const int*   dst   = (const int*)d_in[8];
    float*       out   = (float*)d_out;

    (void)in_sizes; (void)n_in; (void)out_size;

    // zero: 3.2M float4 per array -> 12800 blocks x 256
    zero_kernel<<<12800, 256>>>();

    // scatter: 1 warp/edge -> 1.6M warps -> 200000 blocks x 256
    scatter_kernel<<<(N_EDGES * 32 + 255) / 256, 256>>>(nfeat, efeat, ew, src, dst);

    // gemm: 64 nodes per block
    gemm_kernel<<<(N_NODES + 63) / 64, 256>>>(nfeat, Wn, bn, We, be, out);
}

// round 2
// speedup vs baseline: 1.4600x; 1.4600x over previous
#include <cuda_runtime.h>
#include <cstdint>

#define N_NODES 100000
#define N_EDGES 1600000
#define D 128
#define SCAN_BLK 1024
#define N_SCAN_BLOCKS ((N_NODES + SCAN_BLK - 1) / SCAN_BLK)   // 98

// ---------------------------------------------------------------------------
// Device scratch (static: runtime allocation forbidden)
// ---------------------------------------------------------------------------
__device__ int   g_cnt [N_NODES];
__device__ int   g_cur [N_NODES];
__device__ int   g_off [N_NODES + 1];
__device__ int   g_bsum[128];
__device__ int   g_eidx[N_EDGES];
__device__ int   g_esrc[N_EDGES];
__device__ float g_ewp [N_EDGES];
__device__ float g_x   [(size_t)N_NODES * 256];   // [neigh_norm(128) | esum_norm(128)]

// ---------------------------------------------------------------------------
// fp32x2 packed FMA helpers (sm_103a)
// ---------------------------------------------------------------------------
__device__ __forceinline__ unsigned long long pack2(float lo, float hi) {
    unsigned long long r;
    asm("mov.b64 %0, {%1, %2};" : "=l"(r) : "f"(lo), "f"(hi));
    return r;
}
__device__ __forceinline__ void unpack2(unsigned long long v, float& lo, float& hi) {
    asm("mov.b64 {%0, %1}, %2;" : "=f"(lo), "=f"(hi) : "l"(v));
}
__device__ __forceinline__ void fma2(unsigned long long& acc,
                                     unsigned long long a, unsigned long long b) {
    asm("fma.rn.f32x2 %0, %1, %2, %0;" : "+l"(acc) : "l"(a), "l"(b));
}

// ---------------------------------------------------------------------------
// K0: zero counters
// ---------------------------------------------------------------------------
__global__ void k_zero() {
    int i = blockIdx.x * blockDim.x + threadIdx.x;
    if (i < N_NODES) { g_cnt[i] = 0; g_cur[i] = 0; }
}

// ---------------------------------------------------------------------------
// K1: histogram of dst
// ---------------------------------------------------------------------------
__global__ __launch_bounds__(256) void k_hist(const int* __restrict__ dst) {
    int e = blockIdx.x * blockDim.x + threadIdx.x;
    if (e < N_EDGES) atomicAdd(&g_cnt[dst[e]], 1);
}

// ---------------------------------------------------------------------------
// K2a: per-block exclusive scan (1024 elements/block)
// ---------------------------------------------------------------------------
__global__ __launch_bounds__(SCAN_BLK) void k_scan1() {
    __shared__ int warp_pfx[32];
    const int tid = threadIdx.x;
    const int i   = blockIdx.x * SCAN_BLK + tid;
    const int v   = (i < N_NODES) ? g_cnt[i] : 0;

    // inclusive warp scan
    int x = v;
#pragma unroll
    for (int o = 1; o < 32; o <<= 1) {
        int y = __shfl_up_sync(0xffffffffu, x, o);
        if ((tid & 31) >= o) x += y;
    }
    if ((tid & 31) == 31) warp_pfx[tid >> 5] = x;
    __syncthreads();
    if (tid < 32) {
        int t = warp_pfx[tid];
        int s = t;
#pragma unroll
        for (int o = 1; o < 32; o <<= 1) {
            int y = __shfl_up_sync(0xffffffffu, s, o);
            if (tid >= o) s += y;
        }
        warp_pfx[tid] = s - t;               // exclusive warp prefix
        if (tid == 31) g_bsum[blockIdx.x] = s;  // block total
    }
    __syncthreads();
    if (i < N_NODES) g_off[i] = (x - v) + warp_pfx[tid >> 5];
}

// ---------------------------------------------------------------------------
// K2b: scan the block totals (single block)
// ---------------------------------------------------------------------------
__global__ __launch_bounds__(128) void k_scan2() {
    __shared__ int s[128];
    const int tid = threadIdx.x;
    const int v = (tid < N_SCAN_BLOCKS) ? g_bsum[tid] : 0;
    s[tid] = v;
    __syncthreads();
#pragma unroll
    for (int o = 1; o < 128; o <<= 1) {
        int y = (tid >= o) ? s[tid - o] : 0;
        __syncthreads();
        s[tid] += y;
        __syncthreads();
    }
    if (tid < N_SCAN_BLOCKS) g_bsum[tid] = s[tid] - v;   // exclusive
}

// ---------------------------------------------------------------------------
// K2c: add block prefixes
// ---------------------------------------------------------------------------
__global__ void k_scan3() {
    int i = blockIdx.x * blockDim.x + threadIdx.x;
    if (i < N_NODES) g_off[i] += g_bsum[i >> 10];
    if (i == 0) g_off[N_NODES] = N_EDGES;
}

// ---------------------------------------------------------------------------
// K3: permute edges into CSR order (payload: eid, src, w)
// ---------------------------------------------------------------------------
__global__ __launch_bounds__(256) void k_perm(const int* __restrict__ src,
                                              const int* __restrict__ dst,
                                              const float* __restrict__ ew) {
    int e = blockIdx.x * blockDim.x + threadIdx.x;
    if (e >= N_EDGES) return;
    const int d   = dst[e];
    const int pos = g_off[d] + atomicAdd(&g_cur[d], 1);
    g_eidx[pos] = e;
    g_esrc[pos] = src[e];
    g_ewp [pos] = ew[e];
}

// ---------------------------------------------------------------------------
// K4: warp-per-node gather + normalize. Writes g_x[n][0:128]=x1, [128:256]=x2.
// ---------------------------------------------------------------------------
__global__ __launch_bounds__(256) void k_gather(const float* __restrict__ nfeat,
                                                const float* __restrict__ efeat) {
    const int gtid = blockIdx.x * blockDim.x + threadIdx.x;
    const int n    = gtid >> 5;
    const int lane = threadIdx.x & 31;
    if (n >= N_NODES) return;

    const int beg = __ldg(g_off + n);
    const int end = __ldg(g_off + n + 1);

    float4 accn = make_float4(0.f, 0.f, 0.f, 0.f);
    float4 acce = make_float4(0.f, 0.f, 0.f, 0.f);

    int i = beg;
    if (i < end) {
        int   eid = __ldg(g_eidx + i);
        int   s   = __ldg(g_esrc + i);
        float w   = __ldg(g_ewp  + i);
        for (;;) {
            const float4 ef = __ldg(reinterpret_cast<const float4*>(efeat + (size_t)eid * D) + lane);
            const float4 nf = __ldg(reinterpret_cast<const float4*>(nfeat + (size_t)s   * D) + lane);
            const int ni = i + 1;
            const bool more = ni < end;
            int neid = 0, ns = 0; float nw = 0.f;
            if (more) {            // prefetch next edge meta during the big loads' latency
                neid = __ldg(g_eidx + ni);
                ns   = __ldg(g_esrc + ni);
                nw   = __ldg(g_ewp  + ni);
            }
            acce.x += ef.x; acce.y += ef.y; acce.z += ef.z; acce.w += ef.w;
            accn.x += w * nf.x; accn.y += w * nf.y; accn.z += w * nf.z; accn.w += w * nf.w;
            if (!more) break;
            i = ni; eid = neid; s = ns; w = nw;
        }
    }

    const float deg = (float)(end - beg);
    const float rd1 = 1.f / (deg + 1.f);
    const float rd2 = 1.f / fmaxf(deg, 1.f);

    const float4 self = __ldg(reinterpret_cast<const float4*>(nfeat + (size_t)n * D) + lane);
    float4 x1, x2;
    x1.x = (accn.x + 2.f * self.x) * rd1;
    x1.y = (accn.y + 2.f * self.y) * rd1;
    x1.z = (accn.z + 2.f * self.z) * rd1;
    x1.w = (accn.w + 2.f * self.w) * rd1;
    x2.x = acce.x * rd2; x2.y = acce.y * rd2;
    x2.z = acce.z * rd2; x2.w = acce.w * rd2;

    float* xrow = g_x + (size_t)n * 256;
    reinterpret_cast<float4*>(xrow)[lane]      = x1;
    reinterpret_cast<float4*>(xrow + 128)[lane] = x2;
}

// ---------------------------------------------------------------------------
// K5: GEMM  out[100k,128] = g_x[100k,256] @ Wcat^T + bn + flag*be
// BM=64, BN=128, BK=32; 256 threads; thread tile = 4 row-pairs x 4 cols, FFMA2.
// ---------------------------------------------------------------------------
__global__ __launch_bounds__(256) void k_gemm(const float* __restrict__ Wn,
                                              const float* __restrict__ bn,
                                              const float* __restrict__ We,
                                              const float* __restrict__ be,
                                              float*       __restrict__ out) {
    __shared__ float As[32][64];
    __shared__ float Bs[32][128];
    __shared__ float s_flag[64];

    const int tid = threadIdx.x;
    const int n0  = blockIdx.x * 64;

    if (tid < 64) {
        const int n = n0 + tid;
        float flag = 0.f;
        if (n < N_NODES) flag = (g_off[n + 1] - g_off[n] > 0) ? 1.f : 0.f;
        s_flag[tid] = flag;
    }

    unsigned long long acc2[4][4];
#pragma unroll
    for (int p = 0; p < 4; p++)
#pragma unroll
        for (int j = 0; j < 4; j++) acc2[p][j] = 0ull;

    const int tr = tid >> 5;   // warp id -> rows tr*8 .. tr*8+7
    const int tc = tid & 31;   // lane    -> cols tc*4 .. tc*4+3

    // A loader: 8 floats (2 float4) per thread
    const int  lm   = tid >> 2;
    const int  lv   = tid & 3;
    const int  ln   = n0 + lm;
    const bool lval = ln < N_NODES;

    // B loader: 16 floats (4 float4) per thread
    const int wj = tid >> 1;
    const int wv = tid & 1;

#pragma unroll 1
    for (int k0 = 0; k0 < 256; k0 += 32) {
        // ---- load x tile ----
#pragma unroll
        for (int t = 0; t < 2; t++) {
            const int kk = lv * 4 + t * 16;
            float4 v = make_float4(0.f, 0.f, 0.f, 0.f);
            if (lval)
                v = *reinterpret_cast<const float4*>(g_x + (size_t)ln * 256 + k0 + kk);
            As[kk + 0][lm] = v.x;
            As[kk + 1][lm] = v.y;
            As[kk + 2][lm] = v.z;
            As[kk + 3][lm] = v.w;
        }
        // ---- load W tile ----
        const bool  half1 = (k0 < 128);
        const float* Wp   = half1 ? Wn : We;
        const int   kb    = half1 ? k0 : (k0 - 128);
#pragma unroll
        for (int q = 0; q < 4; q++) {
            const int kk = wv * 16 + q * 4;
            float4 v = __ldg(reinterpret_cast<const float4*>(Wp + (size_t)wj * D + kb + kk));
            Bs[kk + 0][wj] = v.x;
            Bs[kk + 1][wj] = v.y;
            Bs[kk + 2][wj] = v.z;
            Bs[kk + 3][wj] = v.w;
        }
        __syncthreads();

        // ---- compute: packed f32x2 FMAs ----
#pragma unroll
        for (int kk = 0; kk < 32; kk++) {
            const float4 b4 = *reinterpret_cast<const float4*>(&Bs[kk][tc * 4]);
            unsigned long long bb[4];
            bb[0] = pack2(b4.x, b4.x);
            bb[1] = pack2(b4.y, b4.y);
            bb[2] = pack2(b4.z, b4.z);
            bb[3] = pack2(b4.w, b4.w);
            const unsigned long long* ar =
                reinterpret_cast<const unsigned long long*>(&As[kk][tr * 8]);
#pragma unroll
            for (int p = 0; p < 4; p++) {
                const unsigned long long ap = ar[p];
                fma2(acc2[p][0], ap, bb[0]);
                fma2(acc2[p][1], ap, bb[1]);
                fma2(acc2[p][2], ap, bb[2]);
                fma2(acc2[p][3], ap, bb[3]);
            }
        }
        __syncthreads();
    }

    // ---- epilogue ----
    const float4 bnv = __ldg(reinterpret_cast<const float4*>(bn + tc * 4));
    const float4 bev = __ldg(reinterpret_cast<const float4*>(be + tc * 4));
#pragma unroll
    for (int p = 0; p < 4; p++) {
        float lo[4], hi[4];
#pragma unroll
        for (int j = 0; j < 4; j++) unpack2(acc2[p][j], lo[j], hi[j]);

        const int r0 = n0 + tr * 8 + 2 * p;
#pragma unroll
        for (int h = 0; h < 2; h++) {
            const int n = r0 + h;
            if (n < N_NODES) {
                const float f = s_flag[tr * 8 + 2 * p + h];
                const float* a = h ? hi : lo;
                float4 o;
                o.x = a[0] + bnv.x + f * bev.x;
                o.y = a[1] + bnv.y + f * bev.y;
                o.z = a[2] + bnv.z + f * bev.z;
                o.w = a[3] + bnv.w + f * bev.w;
                *reinterpret_cast<float4*>(out + (size_t)n * D + tc * 4) = o;
            }
        }
    }
}

// ---------------------------------------------------------------------------
extern "C" void kernel_launch(void* const* d_in, const int* in_sizes, int n_in,
                              void* d_out, int out_size) {
    const float* nfeat = (const float*)d_in[0];
    const float* efeat = (const float*)d_in[1];
    const float* ew    = (const float*)d_in[2];
    const float* Wn    = (const float*)d_in[3];
    const float* bn    = (const float*)d_in[4];
    const float* We    = (const float*)d_in[5];
    const float* be    = (const float*)d_in[6];
    const int*   src   = (const int*)d_in[7];
    const int*   dst   = (const int*)d_in[8];
    float*       out   = (float*)d_out;

    (void)in_sizes; (void)n_in; (void)out_size;

    k_zero <<<(N_NODES + 255) / 256, 256>>>();
    k_hist <<<(N_EDGES + 255) / 256, 256>>>(dst);
    k_scan1<<<N_SCAN_BLOCKS, SCAN_BLK>>>();
    k_scan2<<<1, 128>>>();
    k_scan3<<<(N_NODES + 255) / 256, 256>>>();
    k_perm <<<(N_EDGES + 255) / 256, 256>>>(src, dst, ew);
    k_gather<<<(N_NODES * 32 + 255) / 256, 256>>>(nfeat, efeat);
    k_gemm <<<(N_NODES + 63) / 64, 256>>>(Wn, bn, We, be, out);
}

// round 3
// speedup vs baseline: 1.4950x; 1.0240x over previous
#include <cuda_runtime.h>
#include <cstdint>

#define N_NODES 100000
#define N_EDGES 1600000
#define D 128
#define SCAN_BLK 1024
#define N_SCAN_BLOCKS ((N_NODES + SCAN_BLK - 1) / SCAN_BLK)   // 98

// ---------------------------------------------------------------------------
// Device scratch
// ---------------------------------------------------------------------------
__device__ int   g_cnt [N_NODES];
__device__ int   g_cur [N_NODES];
__device__ int   g_off [N_NODES + 1];
__device__ int   g_bsum[128];
__device__ int   g_eidx[N_EDGES];
__device__ int   g_esrc[N_EDGES];
__device__ float g_ewp [N_EDGES];
__device__ float g_x   [(size_t)N_NODES * 256];   // [x1(128) | x2(128)]

// ---------------------------------------------------------------------------
// fp32x2 packed FMA helpers
// ---------------------------------------------------------------------------
__device__ __forceinline__ unsigned long long pack2(float lo, float hi) {
    unsigned long long r;
    asm("mov.b64 %0, {%1, %2};" : "=l"(r) : "f"(lo), "f"(hi));
    return r;
}
__device__ __forceinline__ void unpack2(unsigned long long v, float& lo, float& hi) {
    asm("mov.b64 {%0, %1}, %2;" : "=f"(lo), "=f"(hi) : "l"(v));
}
__device__ __forceinline__ void fma2(unsigned long long& acc,
                                     unsigned long long a, unsigned long long b) {
    asm("fma.rn.f32x2 %0, %1, %2, %0;" : "+l"(acc) : "l"(a), "l"(b));
}

// ---------------------------------------------------------------------------
__global__ void k_zero() {
    int i = blockIdx.x * blockDim.x + threadIdx.x;
    if (i < N_NODES) { g_cnt[i] = 0; g_cur[i] = 0; }
}

__global__ __launch_bounds__(256) void k_hist(const int* __restrict__ dst) {
    int e = blockIdx.x * blockDim.x + threadIdx.x;
    if (e < N_EDGES) atomicAdd(&g_cnt[dst[e]], 1);
}

__global__ __launch_bounds__(SCAN_BLK) void k_scan1() {
    __shared__ int warp_pfx[32];
    const int tid = threadIdx.x;
    const int i   = blockIdx.x * SCAN_BLK + tid;
    const int v   = (i < N_NODES) ? g_cnt[i] : 0;

    int x = v;
#pragma unroll
    for (int o = 1; o < 32; o <<= 1) {
        int y = __shfl_up_sync(0xffffffffu, x, o);
        if ((tid & 31) >= o) x += y;
    }
    if ((tid & 31) == 31) warp_pfx[tid >> 5] = x;
    __syncthreads();
    if (tid < 32) {
        int t = warp_pfx[tid];
        int s = t;
#pragma unroll
        for (int o = 1; o < 32; o <<= 1) {
            int y = __shfl_up_sync(0xffffffffu, s, o);
            if (tid >= o) s += y;
        }
        warp_pfx[tid] = s - t;
        if (tid == 31) g_bsum[blockIdx.x] = s;
    }
    __syncthreads();
    if (i < N_NODES) g_off[i] = (x - v) + warp_pfx[tid >> 5];
}

__global__ __launch_bounds__(128) void k_scan2() {
    __shared__ int s[128];
    const int tid = threadIdx.x;
    const int v = (tid < N_SCAN_BLOCKS) ? g_bsum[tid] : 0;
    s[tid] = v;
    __syncthreads();
#pragma unroll
    for (int o = 1; o < 128; o <<= 1) {
        int y = (tid >= o) ? s[tid - o] : 0;
        __syncthreads();
        s[tid] += y;
        __syncthreads();
    }
    if (tid < N_SCAN_BLOCKS) g_bsum[tid] = s[tid] - v;
}

__global__ void k_scan3() {
    int i = blockIdx.x * blockDim.x + threadIdx.x;
    if (i < N_NODES) g_off[i] += g_bsum[i >> 10];
    if (i == 0) g_off[N_NODES] = N_EDGES;
}

__global__ __launch_bounds__(256) void k_perm(const int* __restrict__ src,
                                              const int* __restrict__ dst,
                                              const float* __restrict__ ew) {
    int e = blockIdx.x * blockDim.x + threadIdx.x;
    if (e >= N_EDGES) return;
    const int d   = dst[e];
    const int pos = g_off[d] + atomicAdd(&g_cur[d], 1);
    g_eidx[pos] = e;
    g_esrc[pos] = src[e];
    g_ewp [pos] = ew[e];
}

// ---------------------------------------------------------------------------
// K4: warp-per-node gather, 4-edge unrolled (MLP=8 big loads in flight)
// ---------------------------------------------------------------------------
__global__ __launch_bounds__(256) void k_gather(const float* __restrict__ nfeat,
                                                const float* __restrict__ efeat) {
    const int gtid = blockIdx.x * blockDim.x + threadIdx.x;
    const int n    = gtid >> 5;
    const int lane = threadIdx.x & 31;
    if (n >= N_NODES) return;

    const int beg = __ldg(g_off + n);
    const int end = __ldg(g_off + n + 1);

    float4 accn = make_float4(0.f, 0.f, 0.f, 0.f);
    float4 acce = make_float4(0.f, 0.f, 0.f, 0.f);

    int i = beg;
    for (; i + 3 < end; i += 4) {
        int   e0 = __ldg(g_eidx + i + 0), e1 = __ldg(g_eidx + i + 1);
        int   e2 = __ldg(g_eidx + i + 2), e3 = __ldg(g_eidx + i + 3);
        int   s0 = __ldg(g_esrc + i + 0), s1 = __ldg(g_esrc + i + 1);
        int   s2 = __ldg(g_esrc + i + 2), s3 = __ldg(g_esrc + i + 3);
        float w0 = __ldg(g_ewp + i + 0),  w1 = __ldg(g_ewp + i + 1);
        float w2 = __ldg(g_ewp + i + 2),  w3 = __ldg(g_ewp + i + 3);

        const float4 f0 = __ldg(reinterpret_cast<const float4*>(efeat + (size_t)e0 * D) + lane);
        const float4 f1 = __ldg(reinterpret_cast<const float4*>(efeat + (size_t)e1 * D) + lane);
        const float4 f2 = __ldg(reinterpret_cast<const float4*>(efeat + (size_t)e2 * D) + lane);
        const float4 f3 = __ldg(reinterpret_cast<const float4*>(efeat + (size_t)e3 * D) + lane);
        const float4 m0 = __ldg(reinterpret_cast<const float4*>(nfeat + (size_t)s0 * D) + lane);
        const float4 m1 = __ldg(reinterpret_cast<const float4*>(nfeat + (size_t)s1 * D) + lane);
        const float4 m2 = __ldg(reinterpret_cast<const float4*>(nfeat + (size_t)s2 * D) + lane);
        const float4 m3 = __ldg(reinterpret_cast<const float4*>(nfeat + (size_t)s3 * D) + lane);

        acce.x += (f0.x + f1.x) + (f2.x + f3.x);
        acce.y += (f0.y + f1.y) + (f2.y + f3.y);
        acce.z += (f0.z + f1.z) + (f2.z + f3.z);
        acce.w += (f0.w + f1.w) + (f2.w + f3.w);
        accn.x += (w0 * m0.x + w1 * m1.x) + (w2 * m2.x + w3 * m3.x);
        accn.y += (w0 * m0.y + w1 * m1.y) + (w2 * m2.y + w3 * m3.y);
        accn.z += (w0 * m0.z + w1 * m1.z) + (w2 * m2.z + w3 * m3.z);
        accn.w += (w0 * m0.w + w1 * m1.w) + (w2 * m2.w + w3 * m3.w);
    }
    for (; i < end; i++) {
        const int   e = __ldg(g_eidx + i);
        const int   s = __ldg(g_esrc + i);
        const float w = __ldg(g_ewp  + i);
        const float4 f = __ldg(reinterpret_cast<const float4*>(efeat + (size_t)e * D) + lane);
        const float4 m = __ldg(reinterpret_cast<const float4*>(nfeat + (size_t)s * D) + lane);
        acce.x += f.x; acce.y += f.y; acce.z += f.z; acce.w += f.w;
        accn.x += w * m.x; accn.y += w * m.y; accn.z += w * m.z; accn.w += w * m.w;
    }

    const float deg = (float)(end - beg);
    const float rd1 = 1.f / (deg + 1.f);
    const float rd2 = 1.f / fmaxf(deg, 1.f);

    const float4 self = __ldg(reinterpret_cast<const float4*>(nfeat + (size_t)n * D) + lane);
    float4 x1, x2;
    x1.x = (accn.x + 2.f * self.x) * rd1;
    x1.y = (accn.y + 2.f * self.y) * rd1;
    x1.z = (accn.z + 2.f * self.z) * rd1;
    x1.w = (accn.w + 2.f * self.w) * rd1;
    x2.x = acce.x * rd2; x2.y = acce.y * rd2;
    x2.z = acce.z * rd2; x2.w = acce.w * rd2;

    float* xrow = g_x + (size_t)n * 256;
    reinterpret_cast<float4*>(xrow)[lane]       = x1;
    reinterpret_cast<float4*>(xrow + 128)[lane] = x2;
}

// ---------------------------------------------------------------------------
// K5: GEMM with double-buffered smem.  out = g_x @ Wcat^T + bn + flag*be
// BM=64, BN=128, BK=32, 256 threads, FFMA2 thread tile 4 row-pairs x 4 cols.
// ---------------------------------------------------------------------------
__global__ __launch_bounds__(256) void k_gemm(const float* __restrict__ Wn,
                                              const float* __restrict__ bn,
                                              const float* __restrict__ We,
                                              const float* __restrict__ be,
                                              float*       __restrict__ out) {
    __shared__ float As[2][32][64];
    __shared__ float Bs[2][32][128];
    __shared__ float s_flag[64];

    const int tid = threadIdx.x;
    const int n0  = blockIdx.x * 64;

    if (tid < 64) {
        const int n = n0 + tid;
        float flag = 0.f;
        if (n < N_NODES) flag = (g_off[n + 1] - g_off[n] > 0) ? 1.f : 0.f;
        s_flag[tid] = flag;
    }

    unsigned long long acc2[4][4];
#pragma unroll
    for (int p = 0; p < 4; p++)
#pragma unroll
        for (int j = 0; j < 4; j++) acc2[p][j] = 0ull;

    const int tr = tid >> 5;
    const int tc = tid & 31;

    // A loader: 2 float4 per thread
    const int  lm   = tid >> 2;
    const int  lv   = tid & 3;
    const int  ln   = n0 + lm;
    const bool lval = ln < N_NODES;

    // B loader: 4 float4 per thread
    const int wj = tid >> 1;
    const int wv = tid & 1;

    float4 ra[2];   // A staging
    float4 rb[4];   // B staging

    auto load_tile = [&](int k0, float4* a, float4* b) {
#pragma unroll
        for (int t = 0; t < 2; t++) {
            const int kk = lv * 4 + t * 16;
            a[t] = make_float4(0.f, 0.f, 0.f, 0.f);
            if (lval)
                a[t] = *reinterpret_cast<const float4*>(g_x + (size_t)ln * 256 + k0 + kk);
        }
        const bool  half1 = (k0 < 128);
        const float* Wp   = half1 ? Wn : We;
        const int   kb    = half1 ? k0 : (k0 - 128);
#pragma unroll
        for (int q = 0; q < 4; q++) {
            const int kk = wv * 16 + q * 4;
            b[q] = __ldg(reinterpret_cast<const float4*>(Wp + (size_t)wj * D + kb + kk));
        }
    };
    auto store_tile = [&](int buf, const float4* a, const float4* b) {
#pragma unroll
        for (int t = 0; t < 2; t++) {
            const int kk = lv * 4 + t * 16;
            As[buf][kk + 0][lm] = a[t].x;
            As[buf][kk + 1][lm] = a[t].y;
            As[buf][kk + 2][lm] = a[t].z;
            As[buf][kk + 3][lm] = a[t].w;
        }
#pragma unroll
        for (int q = 0; q < 4; q++) {
            const int kk = wv * 16 + q * 4;
            Bs[buf][kk + 0][wj] = b[q].x;
            Bs[buf][kk + 1][wj] = b[q].y;
            Bs[buf][kk + 2][wj] = b[q].z;
            Bs[buf][kk + 3][wj] = b[q].w;
        }
    };

    load_tile(0, ra, rb);
    store_tile(0, ra, rb);
    __syncthreads();

#pragma unroll
    for (int it = 0; it < 8; it++) {
        const int buf = it & 1;
        if (it < 7) load_tile((it + 1) * 32, ra, rb);   // overlap with compute

#pragma unroll
        for (int kk = 0; kk < 32; kk++) {
            const float4 b4 = *reinterpret_cast<const float4*>(&Bs[buf][kk][tc * 4]);
            unsigned long long bb[4];
            bb[0] = pack2(b4.x, b4.x);
            bb[1] = pack2(b4.y, b4.y);
            bb[2] = pack2(b4.z, b4.z);
            bb[3] = pack2(b4.w, b4.w);
            const unsigned long long* ar =
                reinterpret_cast<const unsigned long long*>(&As[buf][kk][tr * 8]);
#pragma unroll
            for (int p = 0; p < 4; p++) {
                const unsigned long long ap = ar[p];
                fma2(acc2[p][0], ap, bb[0]);
                fma2(acc2[p][1], ap, bb[1]);
                fma2(acc2[p][2], ap, bb[2]);
                fma2(acc2[p][3], ap, bb[3]);
            }
        }

        if (it < 7) {
            store_tile(buf ^ 1, ra, rb);
            __syncthreads();
        }
    }

    // ---- epilogue ----
    const float4 bnv = __ldg(reinterpret_cast<const float4*>(bn + tc * 4));
    const float4 bev = __ldg(reinterpret_cast<const float4*>(be + tc * 4));
#pragma unroll
    for (int p = 0; p < 4; p++) {
        float lo[4], hi[4];
#pragma unroll
        for (int j = 0; j < 4; j++) unpack2(acc2[p][j], lo[j], hi[j]);

        const int r0 = n0 + tr * 8 + 2 * p;
#pragma unroll
        for (int h = 0; h < 2; h++) {
            const int n = r0 + h;
            if (n < N_NODES) {
                const float f = s_flag[tr * 8 + 2 * p + h];
                const float* a = h ? hi : lo;
                float4 o;
                o.x = a[0] + bnv.x + f * bev.x;
                o.y = a[1] + bnv.y + f * bev.y;
                o.z = a[2] + bnv.z + f * bev.z;
                o.w = a[3] + bnv.w + f * bev.w;
                *reinterpret_cast<float4*>(out + (size_t)n * D + tc * 4) = o;
            }
        }
    }
}

// ---------------------------------------------------------------------------
extern "C" void kernel_launch(void* const* d_in, const int* in_sizes, int n_in,
                              void* d_out, int out_size) {
    const float* nfeat = (const float*)d_in[0];
    const float* efeat = (const float*)d_in[1];
    const float* ew    = (const float*)d_in[2];
    const float* Wn    = (const float*)d_in[3];
    const float* bn    = (const float*)d_in[4];
    const float* We    = (const float*)d_in[5];
    const float* be    = (const float*)d_in[6];
    const int*   src   = (const int*)d_in[7];
    const int*   dst   = (const int*)d_in[8];
    float*       out   = (float*)d_out;

    (void)in_sizes; (void)n_in; (void)out_size;

    k_zero <<<(N_NODES + 255) / 256, 256>>>();
    k_hist <<<(N_EDGES + 255) / 256, 256>>>(dst);
    k_scan1<<<N_SCAN_BLOCKS, SCAN_BLK>>>();
    k_scan2<<<1, 128>>>();
    k_scan3<<<(N_NODES + 255) / 256, 256>>>();
    k_perm <<<(N_EDGES + 255) / 256, 256>>>(src, dst, ew);
    k_gather<<<(N_NODES * 32 + 255) / 256, 256>>>(nfeat, efeat);
    k_gemm <<<(N_NODES + 63) / 64, 256>>>(Wn, bn, We, be, out);
}